// round 6
// baseline (speedup 1.0000x reference)
#include <cuda_runtime.h>

#define Bx 2
#define Sx 2048
#define EMBED 1024
#define HEADS 16
#define HEAD 64
#define LA 68   // stride for natural-layout buffers (LDS.32 a/b-frags, 4g+t4)
#define LP 72   // stride for pair-packed / V buffers (LDS.64 frags, 8g+2t4 / 8t4+g)

// ---- scratch (static device globals) ----
__device__ float g_q[Bx*HEADS*Sx*HEAD];   // [bh][s][d] natural, tf32-rounded
__device__ float g_k[Bx*HEADS*Sx*HEAD];   // [bh][s][d] d PAIR-PACKED, tf32-rounded
__device__ float g_v[Bx*HEADS*Sx*HEAD];   // [bh][s][d] natural, tf32-rounded
__device__ float g_attn[Bx*Sx*EMBED];     // [b*S+s][e] e PAIR-PACKED, tf32-rounded
__device__ float g_wo[EMBED*EMBED];       // Wo tf32-rounded, e PAIR-PACKED

__device__ __forceinline__ float f2tff(float f) {
    unsigned u;
    asm("cvt.rna.tf32.f32 %0, %1;" : "=r"(u) : "f"(f));
    return __uint_as_float(u);
}
__device__ __forceinline__ unsigned uf(float f) { return __float_as_uint(f); }
__device__ __forceinline__ float ex2(float x) {
    float y; asm("ex2.approx.ftz.f32 %0, %1;" : "=f"(y) : "f"(x)); return y;
}
__device__ __forceinline__ void cp16(unsigned dst, const void* src) {
    asm volatile("cp.async.cg.shared.global [%0], [%1], 16;" :: "r"(dst), "l"(src));
}
__device__ __forceinline__ unsigned s2u(const void* p) {
    return (unsigned)__cvta_generic_to_shared(p);
}

__device__ __forceinline__ void mma8(float c[4], const unsigned a[4], const unsigned b[2]) {
    asm volatile(
        "mma.sync.aligned.m16n8k8.row.col.f32.tf32.tf32.f32 "
        "{%0,%1,%2,%3}, {%4,%5,%6,%7}, {%8,%9}, {%0,%1,%2,%3};"
        : "+f"(c[0]), "+f"(c[1]), "+f"(c[2]), "+f"(c[3])
        : "r"(a[0]), "r"(a[1]), "r"(a[2]), "r"(a[3]), "r"(b[0]), "r"(b[1]));
}

// ============================================================
// Wo prep: tf32-round + pair-permute each aligned 8-group:
// packed[2i]=orig[i], packed[2i+1]=orig[i+4]
// ============================================================
__global__ __launch_bounds__(256) void prep_wo(const float* __restrict__ Wo)
{
    int grp = blockIdx.x * 256 + threadIdx.x;
    const float4* src = (const float4*)(Wo + (size_t)grp * 8);
    float4 v0 = src[0], v1 = src[1];
    float4* dst = (float4*)(g_wo + (size_t)grp * 8);
    dst[0] = make_float4(f2tff(v0.x), f2tff(v1.x), f2tff(v0.y), f2tff(v1.y));
    dst[1] = make_float4(f2tff(v0.z), f2tff(v1.z), f2tff(v0.w), f2tff(v1.w));
}

// ============================================================
// Per-head projections. grid (S/128, B*H, 3), 256 thr, warp=16 rows.
// K output (z==1) stores d pair-packed for LDS.64 b-frags in attn.
// ============================================================
__global__ __launch_bounds__(256) void proj_kernel(
    const float* __restrict__ vin, const float* __restrict__ kin,
    const float* __restrict__ qin,
    const float* __restrict__ Wv, const float* __restrict__ Wk,
    const float* __restrict__ Wq)
{
    extern __shared__ float sm[];
    float* Xs = sm;            // 128 x LA
    float* Ws = Xs + 128*LA;   //  64 x LA
    const int s0 = blockIdx.x * 128;
    const int bh = blockIdx.y;
    const int b = bh >> 4, h = bh & 15;
    const float* x; const float* W; float* out;
    if (blockIdx.z == 0)      { x = vin; W = Wv; out = g_v; }
    else if (blockIdx.z == 1) { x = kin; W = Wk; out = g_k; }
    else                      { x = qin; W = Wq; out = g_q; }
    const int tid = threadIdx.x;

    #pragma unroll 4
    for (int t = tid; t < 2048; t += 256) {
        int row = t >> 4, c4 = (t & 15) << 2;
        float4 v = *(const float4*)(x + ((size_t)(b*Sx + s0 + row)*HEADS + h)*HEAD + c4);
        *(float4*)&Xs[row*LA + c4] =
            make_float4(f2tff(v.x), f2tff(v.y), f2tff(v.z), f2tff(v.w));
    }
    for (int t = tid; t < 1024; t += 256) {
        int row = t >> 4, c4 = (t & 15) << 2;   // row = d
        float4 v = *(const float4*)(W + row*64 + c4);
        *(float4*)&Ws[row*LA + c4] =
            make_float4(f2tff(v.x), f2tff(v.y), f2tff(v.z), f2tff(v.w));
    }
    __syncthreads();

    const int w = tid >> 5, lane = tid & 31;
    const int g = lane >> 2, t4 = lane & 3;
    float acc[8][4] = {};
    const float* X0 = Xs + (16*w + g)*LA;
    #pragma unroll
    for (int ks = 0; ks < 8; ks++) {
        const int k = ks*8 + t4;
        unsigned a[4] = { uf(X0[k]), uf(X0[8*LA + k]), uf(X0[k+4]), uf(X0[8*LA + k+4]) };
        #pragma unroll
        for (int nt = 0; nt < 8; nt++) {
            const float* Wr = Ws + (nt*8 + g)*LA + k;
            unsigned bb[2] = { uf(Wr[0]), uf(Wr[4]) };
            mma8(acc[nt], a, bb);
        }
    }
    float* o0 = out + (size_t)bh*Sx*HEAD + (size_t)(s0 + 16*w + g)*HEAD;
    float* o1 = o0 + 8*HEAD;
    if (blockIdx.z == 1) {      // K: pair-packed d columns
        const int pp0 = (t4 < 2) ? 4*t4 : 4*t4 - 7;
        #pragma unroll
        for (int nt = 0; nt < 8; nt++) {
            o0[nt*8 + pp0]     = f2tff(acc[nt][0]);
            o0[nt*8 + pp0 + 2] = f2tff(acc[nt][1]);
            o1[nt*8 + pp0]     = f2tff(acc[nt][2]);
            o1[nt*8 + pp0 + 2] = f2tff(acc[nt][3]);
        }
    } else {
        #pragma unroll
        for (int nt = 0; nt < 8; nt++) {
            *(float2*)&o0[nt*8 + 2*t4] =
                make_float2(f2tff(acc[nt][0]), f2tff(acc[nt][1]));
            *(float2*)&o1[nt*8 + 2*t4] =
                make_float2(f2tff(acc[nt][2]), f2tff(acc[nt][3]));
        }
    }
}

// ============================================================
// Flash attention, tf32 mma, causal. grid (B*H, S/128), 256 thr,
// 2 CTAs/SM. q-tile 128 (warp=16 rows), k-tile 64. Q packed into
// a-frag-major smem; K pair-packed (LDS.64 b-frags); cp.async
// double-buffered K/V; P via intra-warp shuffles.
// ============================================================
__global__ __launch_bounds__(256, 2) void attn_kernel()
{
    extern __shared__ float sm[];
    float* Qp = sm;                        // 8w x 8ks x 32 x float4 = 8192 f
    float* KV = sm + 8192;                 // 2 stages x (64*LP K + 64*LP V)
    const int KVST = 2*64*LP;              // 9216 floats per stage

    const int bh = blockIdx.x;
    const int qb = gridDim.y - 1 - blockIdx.y;   // big jobs first
    const int q0 = qb * 128;
    const int tid = threadIdx.x;
    const int w = tid >> 5, lane = tid & 31;
    const int g = lane >> 2, t4 = lane & 3;

    const float* Qg = g_q + (size_t)bh*Sx*HEAD + (size_t)q0*HEAD;
    const float* Kg = g_k + (size_t)bh*Sx*HEAD;
    const float* Vg = g_v + (size_t)bh*Sx*HEAD;
    const int ktN = 2*qb + 2;

    // ---- stage natural Q into KV region, pack a-frag-major ----
    {
        float* Qst = KV;   // 128 x LA = 8704 <= 9216
        #pragma unroll 4
        for (int t = tid; t < 2048; t += 256) {
            int row = t >> 4, c4 = (t & 15) << 2;
            cp16(s2u(&Qst[row*LA + c4]), Qg + row*64 + c4);
        }
        asm volatile("cp.async.commit_group;" ::: "memory");
        asm volatile("cp.async.wait_group 0;" ::: "memory");
        __syncthreads();
        const int r = 16*w + g;
        #pragma unroll
        for (int ks = 0; ks < 8; ks++) {
            const int k = 8*ks + t4;
            float4 v = make_float4(Qst[r*LA + k],     Qst[(r+8)*LA + k],
                                   Qst[r*LA + k + 4], Qst[(r+8)*LA + k + 4]);
            ((float4*)Qp)[(w*8 + ks)*32 + lane] = v;
        }
        __syncthreads();
    }

    // ---- prefetch K/V tile 0 ----
    {
        float* Ks = KV, * Vs = KV + 64*LP;
        #pragma unroll
        for (int t = tid; t < 1024; t += 256) {
            int row = t >> 4, c4 = (t & 15) << 2;
            cp16(s2u(&Ks[row*LP + c4]), Kg + row*64 + c4);
            cp16(s2u(&Vs[row*LP + c4]), Vg + row*64 + c4);
        }
        asm volatile("cp.async.commit_group;" ::: "memory");
    }

    float o[8][4] = {};
    float m_[2] = {-1e30f, -1e30f};
    float l_[2] = {};
    const int rwarp = q0 + 16*w;
    const float SC2 = 0.18033688011112042f;   // 0.125 * log2(e)
    const float4* QP = (const float4*)Qp;

    for (int kt = 0; kt < ktN; kt++) {
        const int cur = kt & 1;
        float* Kc = KV + cur*KVST;
        float* Vc = Kc + 64*LP;
        __syncthreads();
        if (kt + 1 < ktN) {
            float* Kn = KV + (cur^1)*KVST;
            float* Vn = Kn + 64*LP;
            #pragma unroll
            for (int t = tid; t < 1024; t += 256) {
                int row = t >> 4, c4 = (t & 15) << 2;
                cp16(s2u(&Kn[row*LP + c4]), Kg + (size_t)((kt+1)*64 + row)*64 + c4);
                cp16(s2u(&Vn[row*LP + c4]), Vg + (size_t)((kt+1)*64 + row)*64 + c4);
            }
            asm volatile("cp.async.commit_group;" ::: "memory");
            asm volatile("cp.async.wait_group 1;" ::: "memory");
        } else {
            asm volatile("cp.async.wait_group 0;" ::: "memory");
        }
        __syncthreads();

        if (rwarp + 15 >= kt*64) {
            // ---- phase 1: S = Q K^T (K pair-packed -> LDS.64 b-frags) ----
            float sc[8][4] = {};
            #pragma unroll
            for (int ks = 0; ks < 8; ks++) {
                float4 qv = QP[(w*8 + ks)*32 + lane];
                unsigned a[4] = { uf(qv.x), uf(qv.y), uf(qv.z), uf(qv.w) };
                #pragma unroll
                for (int nt = 0; nt < 8; nt++) {
                    float2 kb = *(const float2*)&Kc[(nt*8 + g)*LP + ks*8 + 2*t4];
                    unsigned bb[2] = { uf(kb.x), uf(kb.y) };
                    mma8(sc[nt], a, bb);
                }
            }
            // ---- scale (base-2) + causal mask ----
            #pragma unroll
            for (int nt = 0; nt < 8; nt++)
                #pragma unroll
                for (int i = 0; i < 4; i++)
                    sc[nt][i] *= SC2;
            if (kt*64 + 63 > rwarp) {
                const int rA = rwarp + g, rB = rA + 8;
                #pragma unroll
                for (int nt = 0; nt < 8; nt++) {
                    int c = kt*64 + nt*8 + 2*t4;
                    if (c     > rA) sc[nt][0] = -1e30f;
                    if (c + 1 > rA) sc[nt][1] = -1e30f;
                    if (c     > rB) sc[nt][2] = -1e30f;
                    if (c + 1 > rB) sc[nt][3] = -1e30f;
                }
            }
            // ---- online softmax in registers (base-2) ----
            #pragma unroll
            for (int j = 0; j < 2; j++) {
                float mt0 = -1e30f;
                #pragma unroll
                for (int nt = 0; nt < 8; nt++)
                    mt0 = fmaxf(mt0, fmaxf(sc[nt][2*j], sc[nt][2*j+1]));
                mt0 = fmaxf(mt0, __shfl_xor_sync(0xffffffffu, mt0, 1));
                mt0 = fmaxf(mt0, __shfl_xor_sync(0xffffffffu, mt0, 2));
                float mn = fmaxf(m_[j], mt0);
                float f = ex2(m_[j] - mn);
                m_[j] = mn;
                float s = 0.f;
                #pragma unroll
                for (int nt = 0; nt < 8; nt++) {
                    float p0 = ex2(sc[nt][2*j]   - mn);
                    float p1 = ex2(sc[nt][2*j+1] - mn);
                    s += p0 + p1;
                    sc[nt][2*j] = f2tff(p0); sc[nt][2*j+1] = f2tff(p1);
                }
                s += __shfl_xor_sync(0xffffffffu, s, 1);
                s += __shfl_xor_sync(0xffffffffu, s, 2);
                l_[j] = l_[j]*f + s;
                #pragma unroll
                for (int nt = 0; nt < 8; nt++) {
                    o[nt][2*j] *= f; o[nt][2*j+1] *= f;
                }
            }
            // ---- phase 3: O += P V. P c-frag -> a-frag via shuffles ----
            const int srcA = (lane & 28) | (t4 >> 1);
            const int srcB = srcA + 2;
            const bool par = (t4 & 1);
            #pragma unroll
            for (int ks = 0; ks < 8; ks++) {
                float c0 = sc[ks][0], c1 = sc[ks][1];
                float c2 = sc[ks][2], c3 = sc[ks][3];
                float vA0 = __shfl_sync(0xffffffffu, c0, srcA);
                float vA1 = __shfl_sync(0xffffffffu, c1, srcA);
                float vA2 = __shfl_sync(0xffffffffu, c2, srcA);
                float vA3 = __shfl_sync(0xffffffffu, c3, srcA);
                float vB0 = __shfl_sync(0xffffffffu, c0, srcB);
                float vB1 = __shfl_sync(0xffffffffu, c1, srcB);
                float vB2 = __shfl_sync(0xffffffffu, c2, srcB);
                float vB3 = __shfl_sync(0xffffffffu, c3, srcB);
                unsigned a[4];
                a[0] = uf(par ? vA1 : vA0);
                a[1] = uf(par ? vA3 : vA2);
                a[2] = uf(par ? vB1 : vB0);
                a[3] = uf(par ? vB3 : vB2);
                #pragma unroll
                for (int nt = 0; nt < 8; nt++) {
                    unsigned bb[2] = { uf(Vc[(ks*8 + t4    )*LP + nt*8 + g]),
                                       uf(Vc[(ks*8 + t4 + 4)*LP + nt*8 + g]) };
                    mma8(o[nt], a, bb);
                }
            }
        }
    }

    // ---- epilogue: normalize, tf32-round, scatter PAIR-PACKED ----
    const int b = bh >> 4, h = bh & 15;
    float i0v = 1.0f / l_[0], i1v = 1.0f / l_[1];
    float* d0 = g_attn + (size_t)(b*Sx + q0 + 16*w + g)*EMBED + h*HEAD;
    float* d1 = d0 + (size_t)8*EMBED;
    const int pp0 = (t4 < 2) ? 4*t4 : 4*t4 - 7;
    #pragma unroll
    for (int nt = 0; nt < 8; nt++) {
        d0[nt*8 + pp0]     = f2tff(o[nt][0]*i0v);
        d0[nt*8 + pp0 + 2] = f2tff(o[nt][1]*i0v);
        d1[nt*8 + pp0]     = f2tff(o[nt][2]*i1v);
        d1[nt*8 + pp0 + 2] = f2tff(o[nt][3]*i1v);
    }
}

// ============================================================
// Output projection. grid (EMBED/128, B*S/128), 256 thr, 2 CTAs/SM.
// M=128, N=128, single-buffered K-loop 16x64; A and W pair-packed
// -> all fragment loads are LDS.64, stride 72 conflict-free.
// ============================================================
__global__ __launch_bounds__(256, 2) void outproj_kernel(
    const float* __restrict__ bo, float* __restrict__ out)
{
    extern __shared__ float sm[];
    float* As = sm;              // 128 x LP
    float* Wf = sm + 128*LP;     // 128 x LP
    const int j0 = blockIdx.x * 128;
    const int r0 = blockIdx.y * 128;
    const int tid = threadIdx.x;
    const int w = tid >> 5, lane = tid & 31;
    const int g = lane >> 2, t4 = lane & 3;

    float acc[16][4] = {};
    for (int et = 0; et < 16; et++) {
        const int e0 = et * 64;
        __syncthreads();   // previous compute done before overwrite
        #pragma unroll 4
        for (int t = tid; t < 2048; t += 256) {
            int row = t >> 4, c4 = (t & 15) << 2;
            cp16(s2u(&As[row*LP + c4]),
                 g_attn + (size_t)(r0 + row)*EMBED + e0 + c4);
        }
        #pragma unroll 4
        for (int t = tid; t < 2048; t += 256) {
            int row = t >> 4, c4 = (t & 15) << 2;
            cp16(s2u(&Wf[row*LP + c4]),
                 g_wo + (size_t)(j0 + row)*EMBED + e0 + c4);
        }
        asm volatile("cp.async.commit_group;" ::: "memory");
        asm volatile("cp.async.wait_group 0;" ::: "memory");
        __syncthreads();

        const float* A0 = As + (16*w + g)*LP;
        #pragma unroll
        for (int ks = 0; ks < 8; ks++) {
            float2 xa = *(const float2*)&A0[ks*8 + 2*t4];
            float2 ya = *(const float2*)&A0[8*LP + ks*8 + 2*t4];
            unsigned a[4] = { uf(xa.x), uf(ya.x), uf(xa.y), uf(ya.y) };
            #pragma unroll
            for (int nt = 0; nt < 16; nt++) {
                float2 wb = *(const float2*)&Wf[(nt*8 + g)*LP + ks*8 + 2*t4];
                unsigned bb[2] = { uf(wb.x), uf(wb.y) };
                mma8(acc[nt], a, bb);
            }
        }
    }

    const int row = r0 + 16*w + g;
    #pragma unroll
    for (int nt = 0; nt < 16; nt++) {
        int j = j0 + nt*8 + 2*t4;
        float b0 = bo[j], b1 = bo[j + 1];
        *(float2*)&out[(size_t)row*EMBED + j] =
            make_float2(acc[nt][0] + b0, acc[nt][1] + b1);
        *(float2*)&out[(size_t)(row + 8)*EMBED + j] =
            make_float2(acc[nt][2] + b0, acc[nt][3] + b1);
    }
}

// ============================================================
extern "C" void kernel_launch(void* const* d_in, const int* in_sizes, int n_in,
                              void* d_out, int out_size)
{
    const float* values  = (const float*)d_in[0];
    const float* keys    = (const float*)d_in[1];
    const float* queries = (const float*)d_in[2];
    // d_in[3] = mask: known causal tril, applied analytically — ignored.
    const float* Wv = (const float*)d_in[4];
    const float* Wk = (const float*)d_in[5];
    const float* Wq = (const float*)d_in[6];
    const float* Wo = (const float*)d_in[7];
    const float* bo = (const float*)d_in[8];
    float* out = (float*)d_out;

    const int proj_smem  = (128 + 64) * LA * 4;              //  52224
    const int attn_smem  = (8192 + 2*2*64*LP) * 4;           // 106496
    const int oproj_smem = 2 * 128 * LP * 4;                 //  73728
    cudaFuncSetAttribute(proj_kernel,
        cudaFuncAttributeMaxDynamicSharedMemorySize, proj_smem);
    cudaFuncSetAttribute(attn_kernel,
        cudaFuncAttributeMaxDynamicSharedMemorySize, attn_smem);
    cudaFuncSetAttribute(outproj_kernel,
        cudaFuncAttributeMaxDynamicSharedMemorySize, oproj_smem);

    prep_wo<<<512, 256>>>(Wo);

    dim3 pg(Sx/128, Bx*HEADS, 3);
    proj_kernel<<<pg, 256, proj_smem>>>(values, keys, queries, Wv, Wk, Wq);

    dim3 ag(Bx*HEADS, Sx/128);
    attn_kernel<<<ag, 256, attn_smem>>>();

    dim3 og(EMBED/128, (Bx*Sx)/128);
    outproj_kernel<<<og, 256, oproj_smem>>>(bo, out);
}

// round 7
// speedup vs baseline: 1.1258x; 1.1258x over previous
#include <cuda_runtime.h>

#define Bx 2
#define Sx 2048
#define EMBED 1024
#define HEADS 16
#define HEAD 64
#define LA 68   // stride for natural-layout buffers (LDS.32 a-frags, 4g+t4)
#define LP 72   // stride for pair-packed K / transposed V (LDS.64 frags)

// ---- scratch (static device globals) ----
__device__ float g_q[Bx*HEADS*Sx*HEAD];   // [bh][s][d] natural, tf32-rounded
__device__ float g_k[Bx*HEADS*Sx*HEAD];   // [bh][s][d] d PAIR-PACKED, tf32-rounded
__device__ float g_vt[Bx*HEADS*HEAD*Sx];  // [bh][d][s] TRANSPOSED, tf32-rounded
__device__ float g_attn[Bx*Sx*EMBED];     // [b*S+s][e] e PAIR-PACKED, tf32-rounded
__device__ float g_wo[EMBED*EMBED];       // Wo tf32-rounded, e PAIR-PACKED

__device__ __forceinline__ float f2tff(float f) {
    unsigned u;
    asm("cvt.rna.tf32.f32 %0, %1;" : "=r"(u) : "f"(f));
    return __uint_as_float(u);
}
__device__ __forceinline__ unsigned uf(float f) { return __float_as_uint(f); }
__device__ __forceinline__ float ex2(float x) {
    float y; asm("ex2.approx.ftz.f32 %0, %1;" : "=f"(y) : "f"(x)); return y;
}
__device__ __forceinline__ void cp16(unsigned dst, const void* src) {
    asm volatile("cp.async.cg.shared.global [%0], [%1], 16;" :: "r"(dst), "l"(src));
}
__device__ __forceinline__ unsigned s2u(const void* p) {
    return (unsigned)__cvta_generic_to_shared(p);
}

__device__ __forceinline__ void mma8(float c[4], const unsigned a[4], const unsigned b[2]) {
    asm volatile(
        "mma.sync.aligned.m16n8k8.row.col.f32.tf32.tf32.f32 "
        "{%0,%1,%2,%3}, {%4,%5,%6,%7}, {%8,%9}, {%0,%1,%2,%3};"
        : "+f"(c[0]), "+f"(c[1]), "+f"(c[2]), "+f"(c[3])
        : "r"(a[0]), "r"(a[1]), "r"(a[2]), "r"(a[3]), "r"(b[0]), "r"(b[1]));
}

// ============================================================
// Wo prep: tf32-round + pair-permute each aligned 8-group:
// packed[2i]=orig[i], packed[2i+1]=orig[i+4]
// ============================================================
__global__ __launch_bounds__(256) void prep_wo(const float* __restrict__ Wo)
{
    int grp = blockIdx.x * 256 + threadIdx.x;
    const float4* src = (const float4*)(Wo + (size_t)grp * 8);
    float4 v0 = src[0], v1 = src[1];
    float4* dst = (float4*)(g_wo + (size_t)grp * 8);
    dst[0] = make_float4(f2tff(v0.x), f2tff(v1.x), f2tff(v0.y), f2tff(v1.y));
    dst[1] = make_float4(f2tff(v0.z), f2tff(v1.z), f2tff(v0.w), f2tff(v1.w));
}

// ============================================================
// Per-head projections. grid (S/128, B*H, 3), 256 thr, warp=16 rows.
// z==0: V -> g_vt TRANSPOSED [d][s].  z==1: K -> pair-packed d.
// z==2: Q -> natural.
// ============================================================
__global__ __launch_bounds__(256) void proj_kernel(
    const float* __restrict__ vin, const float* __restrict__ kin,
    const float* __restrict__ qin,
    const float* __restrict__ Wv, const float* __restrict__ Wk,
    const float* __restrict__ Wq)
{
    extern __shared__ float sm[];
    float* Xs = sm;            // 128 x LA
    float* Ws = Xs + 128*LA;   //  64 x LA
    const int s0 = blockIdx.x * 128;
    const int bh = blockIdx.y;
    const int b = bh >> 4, h = bh & 15;
    const float* x; const float* W;
    if (blockIdx.z == 0)      { x = vin; W = Wv; }
    else if (blockIdx.z == 1) { x = kin; W = Wk; }
    else                      { x = qin; W = Wq; }
    const int tid = threadIdx.x;

    #pragma unroll 4
    for (int t = tid; t < 2048; t += 256) {
        int row = t >> 4, c4 = (t & 15) << 2;
        float4 v = *(const float4*)(x + ((size_t)(b*Sx + s0 + row)*HEADS + h)*HEAD + c4);
        *(float4*)&Xs[row*LA + c4] =
            make_float4(f2tff(v.x), f2tff(v.y), f2tff(v.z), f2tff(v.w));
    }
    for (int t = tid; t < 1024; t += 256) {
        int row = t >> 4, c4 = (t & 15) << 2;   // row = d
        float4 v = *(const float4*)(W + row*64 + c4);
        *(float4*)&Ws[row*LA + c4] =
            make_float4(f2tff(v.x), f2tff(v.y), f2tff(v.z), f2tff(v.w));
    }
    __syncthreads();

    const int w = tid >> 5, lane = tid & 31;
    const int g = lane >> 2, t4 = lane & 3;
    float acc[8][4] = {};
    const float* X0 = Xs + (16*w + g)*LA;
    #pragma unroll
    for (int ks = 0; ks < 8; ks++) {
        const int k = ks*8 + t4;
        unsigned a[4] = { uf(X0[k]), uf(X0[8*LA + k]), uf(X0[k+4]), uf(X0[8*LA + k+4]) };
        #pragma unroll
        for (int nt = 0; nt < 8; nt++) {
            const float* Wr = Ws + (nt*8 + g)*LA + k;
            unsigned bb[2] = { uf(Wr[0]), uf(Wr[4]) };
            mma8(acc[nt], a, bb);
        }
    }

    if (blockIdx.z == 0) {      // V: transposed store to g_vt[bh][d][s]
        const int s = s0 + 16*w + g;
        float* vt = g_vt + (size_t)bh*HEAD*Sx;
        #pragma unroll
        for (int nt = 0; nt < 8; nt++) {
            const int d = nt*8 + 2*t4;
            vt[(size_t)d*Sx + s]         = f2tff(acc[nt][0]);
            vt[(size_t)(d+1)*Sx + s]     = f2tff(acc[nt][1]);
            vt[(size_t)d*Sx + s + 8]     = f2tff(acc[nt][2]);
            vt[(size_t)(d+1)*Sx + s + 8] = f2tff(acc[nt][3]);
        }
    } else if (blockIdx.z == 1) {  // K: pair-packed d columns
        float* o0 = g_k + (size_t)bh*Sx*HEAD + (size_t)(s0 + 16*w + g)*HEAD;
        float* o1 = o0 + 8*HEAD;
        const int pp0 = (t4 < 2) ? 4*t4 : 4*t4 - 7;
        #pragma unroll
        for (int nt = 0; nt < 8; nt++) {
            o0[nt*8 + pp0]     = f2tff(acc[nt][0]);
            o0[nt*8 + pp0 + 2] = f2tff(acc[nt][1]);
            o1[nt*8 + pp0]     = f2tff(acc[nt][2]);
            o1[nt*8 + pp0 + 2] = f2tff(acc[nt][3]);
        }
    } else {                     // Q: natural
        float* o0 = g_q + (size_t)bh*Sx*HEAD + (size_t)(s0 + 16*w + g)*HEAD;
        float* o1 = o0 + 8*HEAD;
        #pragma unroll
        for (int nt = 0; nt < 8; nt++) {
            *(float2*)&o0[nt*8 + 2*t4] =
                make_float2(f2tff(acc[nt][0]), f2tff(acc[nt][1]));
            *(float2*)&o1[nt*8 + 2*t4] =
                make_float2(f2tff(acc[nt][2]), f2tff(acc[nt][3]));
        }
    }
}

// ============================================================
// Flash attention, tf32 mma, causal. grid (B*H, S/256), 256 thr,
// 1 CTA/SM. q-tile 256 (warp=32 rows), k-tile 64.
// Q packed a-frag-major; K pair-packed (LDS.64 b-frags);
// V TRANSPOSED in smem -> P c-frag reused directly as a-frag via
// the k-slot permutation (t4->2t4, t4+4->2t4+1): NO exchange at all.
// ============================================================
__global__ __launch_bounds__(256, 1) void attn_kernel()
{
    extern __shared__ float sm[];
    float* Qp = sm;                       // 8w x 2mt x 8ks x 32 x float4 = 16384 f
    float* KV = sm + 16384;               // 2 stages x (64*LP K + 64*LP Vt)
    const int KVST = 2*64*LP;             // 9216 floats per stage

    const int bh = blockIdx.x;
    const int qb = gridDim.y - 1 - blockIdx.y;   // big jobs first
    const int q0 = qb * 256;
    const int tid = threadIdx.x;
    const int w = tid >> 5, lane = tid & 31;
    const int g = lane >> 2, t4 = lane & 3;

    const float* Qg  = g_q  + (size_t)bh*Sx*HEAD + (size_t)q0*HEAD;
    const float* Kg  = g_k  + (size_t)bh*Sx*HEAD;
    const float* Vtg = g_vt + (size_t)bh*HEAD*Sx;
    const int ktN = 4*qb + 4;

    // ---- stage natural Q into KV region, pack a-frag-major ----
    {
        float* Qst = KV;   // 256 x LA = 17408 <= 18432
        #pragma unroll 4
        for (int t = tid; t < 4096; t += 256) {
            int row = t >> 4, c4 = (t & 15) << 2;
            cp16(s2u(&Qst[row*LA + c4]), Qg + row*64 + c4);
        }
        asm volatile("cp.async.commit_group;" ::: "memory");
        asm volatile("cp.async.wait_group 0;" ::: "memory");
        __syncthreads();
        #pragma unroll
        for (int mt = 0; mt < 2; mt++)
            #pragma unroll
            for (int ks = 0; ks < 8; ks++) {
                int r = 32*w + 16*mt + g;
                int k = 8*ks + t4;
                float4 v = make_float4(Qst[r*LA + k],     Qst[(r+8)*LA + k],
                                       Qst[r*LA + k + 4], Qst[(r+8)*LA + k + 4]);
                ((float4*)Qp)[((w*2 + mt)*8 + ks)*32 + lane] = v;
            }
        __syncthreads();
    }

    // ---- prefetch K/Vt tile 0 ----
    {
        float* Ks = KV, * Vs = KV + 64*LP;
        #pragma unroll
        for (int t = tid; t < 1024; t += 256) {
            int row = t >> 4, c4 = (t & 15) << 2;
            cp16(s2u(&Ks[row*LP + c4]), Kg + row*64 + c4);
            cp16(s2u(&Vs[row*LP + c4]), Vtg + (size_t)row*Sx + c4);
        }
        asm volatile("cp.async.commit_group;" ::: "memory");
    }

    float o[2][8][4] = {};
    float m_[4] = {-1e30f, -1e30f, -1e30f, -1e30f};
    float l_[4] = {};
    const int rwarp = q0 + 32*w;
    const float SC2 = 0.18033688011112042f;   // 0.125 * log2(e)
    const float4* QP = (const float4*)Qp;
    const int qbase0 = (w*2 + 0)*8*32;
    const int qbase1 = (w*2 + 1)*8*32;

    for (int kt = 0; kt < ktN; kt++) {
        const int cur = kt & 1;
        float* Kc = KV + cur*KVST;
        float* Vc = Kc + 64*LP;
        __syncthreads();
        if (kt + 1 < ktN) {
            float* Kn = KV + (cur^1)*KVST;
            float* Vn = Kn + 64*LP;
            #pragma unroll
            for (int t = tid; t < 1024; t += 256) {
                int row = t >> 4, c4 = (t & 15) << 2;
                cp16(s2u(&Kn[row*LP + c4]), Kg + (size_t)((kt+1)*64 + row)*64 + c4);
                cp16(s2u(&Vn[row*LP + c4]), Vtg + (size_t)row*Sx + (kt+1)*64 + c4);
            }
            asm volatile("cp.async.commit_group;" ::: "memory");
            asm volatile("cp.async.wait_group 1;" ::: "memory");
        } else {
            asm volatile("cp.async.wait_group 0;" ::: "memory");
        }
        __syncthreads();

        if (rwarp + 31 >= kt*64) {
            // ---- phase 1: S = Q K^T (K pair-packed -> LDS.64) ----
            float sc[2][8][4] = {};
            #pragma unroll
            for (int ks = 0; ks < 8; ks++) {
                float4 q0v = QP[qbase0 + ks*32 + lane];
                float4 q1v = QP[qbase1 + ks*32 + lane];
                unsigned a0[4] = { uf(q0v.x), uf(q0v.y), uf(q0v.z), uf(q0v.w) };
                unsigned a1[4] = { uf(q1v.x), uf(q1v.y), uf(q1v.z), uf(q1v.w) };
                #pragma unroll
                for (int nt = 0; nt < 8; nt++) {
                    float2 kb = *(const float2*)&Kc[(nt*8 + g)*LP + ks*8 + 2*t4];
                    unsigned bb[2] = { uf(kb.x), uf(kb.y) };
                    mma8(sc[0][nt], a0, bb);
                    mma8(sc[1][nt], a1, bb);
                }
            }
            // ---- scale (base-2) + causal mask ----
            #pragma unroll
            for (int mt = 0; mt < 2; mt++)
                #pragma unroll
                for (int nt = 0; nt < 8; nt++)
                    #pragma unroll
                    for (int i = 0; i < 4; i++)
                        sc[mt][nt][i] *= SC2;
            if (kt*64 + 63 > rwarp) {
                #pragma unroll
                for (int mt = 0; mt < 2; mt++) {
                    const int rA = rwarp + 16*mt + g, rB = rA + 8;
                    #pragma unroll
                    for (int nt = 0; nt < 8; nt++) {
                        int c = kt*64 + nt*8 + 2*t4;
                        if (c     > rA) sc[mt][nt][0] = -1e30f;
                        if (c + 1 > rA) sc[mt][nt][1] = -1e30f;
                        if (c     > rB) sc[mt][nt][2] = -1e30f;
                        if (c + 1 > rB) sc[mt][nt][3] = -1e30f;
                    }
                }
            }
            // ---- online softmax in registers (base-2) ----
            #pragma unroll
            for (int j = 0; j < 4; j++) {
                const int mt = j >> 1, p = j & 1;
                float mt0 = -1e30f;
                #pragma unroll
                for (int nt = 0; nt < 8; nt++)
                    mt0 = fmaxf(mt0, fmaxf(sc[mt][nt][2*p], sc[mt][nt][2*p+1]));
                mt0 = fmaxf(mt0, __shfl_xor_sync(0xffffffffu, mt0, 1));
                mt0 = fmaxf(mt0, __shfl_xor_sync(0xffffffffu, mt0, 2));
                float mn = fmaxf(m_[j], mt0);
                float f = ex2(m_[j] - mn);
                m_[j] = mn;
                float s = 0.f;
                #pragma unroll
                for (int nt = 0; nt < 8; nt++) {
                    float p0 = ex2(sc[mt][nt][2*p]   - mn);
                    float p1 = ex2(sc[mt][nt][2*p+1] - mn);
                    s += p0 + p1;
                    sc[mt][nt][2*p] = f2tff(p0); sc[mt][nt][2*p+1] = f2tff(p1);
                }
                s += __shfl_xor_sync(0xffffffffu, s, 1);
                s += __shfl_xor_sync(0xffffffffu, s, 2);
                l_[j] = l_[j]*f + s;
                #pragma unroll
                for (int nt = 0; nt < 8; nt++) {
                    o[mt][nt][2*p] *= f; o[mt][nt][2*p+1] *= f;
                }
            }
            // ---- phase 3: O += P V. c-frag IS the a-frag under the
            // k-slot permutation; V^T supplies matching LDS.64 b-frags ----
            #pragma unroll
            for (int ks = 0; ks < 8; ks++) {
                unsigned a0[4] = { uf(sc[0][ks][0]), uf(sc[0][ks][2]),
                                   uf(sc[0][ks][1]), uf(sc[0][ks][3]) };
                unsigned a1[4] = { uf(sc[1][ks][0]), uf(sc[1][ks][2]),
                                   uf(sc[1][ks][1]), uf(sc[1][ks][3]) };
                #pragma unroll
                for (int nt = 0; nt < 8; nt++) {
                    float2 vb = *(const float2*)&Vc[(nt*8 + g)*LP + ks*8 + 2*t4];
                    unsigned bb[2] = { uf(vb.x), uf(vb.y) };
                    mma8(o[0][nt], a0, bb);
                    mma8(o[1][nt], a1, bb);
                }
            }
        }
    }

    // ---- epilogue: normalize, tf32-round, scatter PAIR-PACKED ----
    const int b = bh >> 4, h = bh & 15;
    const int pp0 = (t4 < 2) ? 4*t4 : 4*t4 - 7;
    #pragma unroll
    for (int mt = 0; mt < 2; mt++) {
        float i0v = 1.0f / l_[2*mt], i1v = 1.0f / l_[2*mt+1];
        float* d0 = g_attn + (size_t)(b*Sx + q0 + 32*w + 16*mt + g)*EMBED + h*HEAD;
        float* d1 = d0 + (size_t)8*EMBED;
        #pragma unroll
        for (int nt = 0; nt < 8; nt++) {
            d0[nt*8 + pp0]     = f2tff(o[mt][nt][0]*i0v);
            d0[nt*8 + pp0 + 2] = f2tff(o[mt][nt][1]*i0v);
            d1[nt*8 + pp0]     = f2tff(o[mt][nt][2]*i1v);
            d1[nt*8 + pp0 + 2] = f2tff(o[mt][nt][3]*i1v);
        }
    }
}

// ============================================================
// Output projection. grid (EMBED/128, B*S/128), 256 thr, 2 CTAs/SM.
// M=128, N=128, single-buffered K-loop 16x64; A and W pair-packed
// -> all fragment loads are LDS.64, stride 72 conflict-free.
// ============================================================
__global__ __launch_bounds__(256, 2) void outproj_kernel(
    const float* __restrict__ bo, float* __restrict__ out)
{
    extern __shared__ float sm[];
    float* As = sm;              // 128 x LP
    float* Wf = sm + 128*LP;     // 128 x LP
    const int j0 = blockIdx.x * 128;
    const int r0 = blockIdx.y * 128;
    const int tid = threadIdx.x;
    const int w = tid >> 5, lane = tid & 31;
    const int g = lane >> 2, t4 = lane & 3;

    float acc[16][4] = {};
    for (int et = 0; et < 16; et++) {
        const int e0 = et * 64;
        __syncthreads();
        #pragma unroll 4
        for (int t = tid; t < 2048; t += 256) {
            int row = t >> 4, c4 = (t & 15) << 2;
            cp16(s2u(&As[row*LP + c4]),
                 g_attn + (size_t)(r0 + row)*EMBED + e0 + c4);
        }
        #pragma unroll 4
        for (int t = tid; t < 2048; t += 256) {
            int row = t >> 4, c4 = (t & 15) << 2;
            cp16(s2u(&Wf[row*LP + c4]),
                 g_wo + (size_t)(j0 + row)*EMBED + e0 + c4);
        }
        asm volatile("cp.async.commit_group;" ::: "memory");
        asm volatile("cp.async.wait_group 0;" ::: "memory");
        __syncthreads();

        const float* A0 = As + (16*w + g)*LP;
        #pragma unroll
        for (int ks = 0; ks < 8; ks++) {
            float2 xa = *(const float2*)&A0[ks*8 + 2*t4];
            float2 ya = *(const float2*)&A0[8*LP + ks*8 + 2*t4];
            unsigned a[4] = { uf(xa.x), uf(ya.x), uf(xa.y), uf(ya.y) };
            #pragma unroll
            for (int nt = 0; nt < 16; nt++) {
                float2 wb = *(const float2*)&Wf[(nt*8 + g)*LP + ks*8 + 2*t4];
                unsigned bb[2] = { uf(wb.x), uf(wb.y) };
                mma8(acc[nt], a, bb);
            }
        }
    }

    const int row = r0 + 16*w + g;
    #pragma unroll
    for (int nt = 0; nt < 16; nt++) {
        int j = j0 + nt*8 + 2*t4;
        float b0 = bo[j], b1 = bo[j + 1];
        *(float2*)&out[(size_t)row*EMBED + j] =
            make_float2(acc[nt][0] + b0, acc[nt][1] + b1);
        *(float2*)&out[(size_t)(row + 8)*EMBED + j] =
            make_float2(acc[nt][2] + b0, acc[nt][3] + b1);
    }
}

// ============================================================
extern "C" void kernel_launch(void* const* d_in, const int* in_sizes, int n_in,
                              void* d_out, int out_size)
{
    const float* values  = (const float*)d_in[0];
    const float* keys    = (const float*)d_in[1];
    const float* queries = (const float*)d_in[2];
    // d_in[3] = mask: known causal tril, applied analytically — ignored.
    const float* Wv = (const float*)d_in[4];
    const float* Wk = (const float*)d_in[5];
    const float* Wq = (const float*)d_in[6];
    const float* Wo = (const float*)d_in[7];
    const float* bo = (const float*)d_in[8];
    float* out = (float*)d_out;

    const int proj_smem  = (128 + 64) * LA * 4;              //  52224
    const int attn_smem  = (16384 + 2*2*64*LP) * 4;          // 139264
    const int oproj_smem = 2 * 128 * LP * 4;                 //  73728
    cudaFuncSetAttribute(proj_kernel,
        cudaFuncAttributeMaxDynamicSharedMemorySize, proj_smem);
    cudaFuncSetAttribute(attn_kernel,
        cudaFuncAttributeMaxDynamicSharedMemorySize, attn_smem);
    cudaFuncSetAttribute(outproj_kernel,
        cudaFuncAttributeMaxDynamicSharedMemorySize, oproj_smem);

    prep_wo<<<512, 256>>>(Wo);

    dim3 pg(Sx/128, Bx*HEADS, 3);
    proj_kernel<<<pg, 256, proj_smem>>>(values, keys, queries, Wv, Wk, Wq);

    dim3 ag(Bx*HEADS, Sx/256);
    attn_kernel<<<ag, 256, attn_smem>>>();

    dim3 og(EMBED/128, (Bx*Sx)/128);
    outproj_kernel<<<og, 256, oproj_smem>>>(bo, out);
}

// round 8
// speedup vs baseline: 1.1280x; 1.0020x over previous
#include <cuda_runtime.h>

#define Bx 2
#define Sx 2048
#define EMBED 1024
#define HEADS 16
#define HEAD 64
#define LA 68   // stride for natural-layout buffers (LDS.32 a-frags, 4g+t4)
#define LP 72   // stride for pair-packed K / transposed V (LDS.64 frags)
#define LO 40   // outproj stage stride (k-chunk 32 + 8 pad), LDS.64 conflict-free

// ---- scratch (static device globals) ----
__device__ float g_q[Bx*HEADS*Sx*HEAD];   // [bh][s][d] natural, tf32-rounded
__device__ float g_k[Bx*HEADS*Sx*HEAD];   // [bh][s][d] d PAIR-PACKED, tf32-rounded
__device__ float g_vt[Bx*HEADS*HEAD*Sx];  // [bh][d][s] TRANSPOSED, tf32-rounded
__device__ float g_attn[Bx*Sx*EMBED];     // [b*S+s][e] e PAIR-PACKED, tf32-rounded
__device__ float g_wo[EMBED*EMBED];       // Wo tf32-rounded, e PAIR-PACKED

__device__ __forceinline__ float f2tff(float f) {
    unsigned u;
    asm("cvt.rna.tf32.f32 %0, %1;" : "=r"(u) : "f"(f));
    return __uint_as_float(u);
}
__device__ __forceinline__ unsigned uf(float f) { return __float_as_uint(f); }
__device__ __forceinline__ float ex2(float x) {
    float y; asm("ex2.approx.ftz.f32 %0, %1;" : "=f"(y) : "f"(x)); return y;
}
__device__ __forceinline__ void cp16(unsigned dst, const void* src) {
    asm volatile("cp.async.cg.shared.global [%0], [%1], 16;" :: "r"(dst), "l"(src));
}
__device__ __forceinline__ unsigned s2u(const void* p) {
    return (unsigned)__cvta_generic_to_shared(p);
}

__device__ __forceinline__ void mma8(float c[4], const unsigned a[4], const unsigned b[2]) {
    asm volatile(
        "mma.sync.aligned.m16n8k8.row.col.f32.tf32.tf32.f32 "
        "{%0,%1,%2,%3}, {%4,%5,%6,%7}, {%8,%9}, {%0,%1,%2,%3};"
        : "+f"(c[0]), "+f"(c[1]), "+f"(c[2]), "+f"(c[3])
        : "r"(a[0]), "r"(a[1]), "r"(a[2]), "r"(a[3]), "r"(b[0]), "r"(b[1]));
}

// ============================================================
// Per-head projections + Wo prep. grid (S/128, B*H, 4), 256 thr.
// z==0: V -> g_vt TRANSPOSED [d][s].  z==1: K -> pair-packed d.
// z==2: Q -> natural.                 z==3: Wo -> g_wo (round+pack).
// ============================================================
__global__ __launch_bounds__(256) void proj_kernel(
    const float* __restrict__ vin, const float* __restrict__ kin,
    const float* __restrict__ qin,
    const float* __restrict__ Wv, const float* __restrict__ Wk,
    const float* __restrict__ Wq, const float* __restrict__ Wo)
{
    if (blockIdx.z == 3) {
        // Wo prep: tf32-round + pair-permute aligned 8-groups:
        // packed[2i]=orig[i], packed[2i+1]=orig[i+4]
        int bid = blockIdx.y * gridDim.x + blockIdx.x;        // 0..511
        int grp = bid * 256 + threadIdx.x;                    // 0..131071
        const float4* src = (const float4*)(Wo + (size_t)grp * 8);
        float4 v0 = src[0], v1 = src[1];
        float4* dst = (float4*)(g_wo + (size_t)grp * 8);
        dst[0] = make_float4(f2tff(v0.x), f2tff(v1.x), f2tff(v0.y), f2tff(v1.y));
        dst[1] = make_float4(f2tff(v0.z), f2tff(v1.z), f2tff(v0.w), f2tff(v1.w));
        return;
    }

    extern __shared__ float sm[];
    float* Xs = sm;            // 128 x LA
    float* Ws = Xs + 128*LA;   //  64 x LA
    const int s0 = blockIdx.x * 128;
    const int bh = blockIdx.y;
    const int b = bh >> 4, h = bh & 15;
    const float* x; const float* W;
    if (blockIdx.z == 0)      { x = vin; W = Wv; }
    else if (blockIdx.z == 1) { x = kin; W = Wk; }
    else                      { x = qin; W = Wq; }
    const int tid = threadIdx.x;

    #pragma unroll 4
    for (int t = tid; t < 2048; t += 256) {
        int row = t >> 4, c4 = (t & 15) << 2;
        float4 v = *(const float4*)(x + ((size_t)(b*Sx + s0 + row)*HEADS + h)*HEAD + c4);
        *(float4*)&Xs[row*LA + c4] =
            make_float4(f2tff(v.x), f2tff(v.y), f2tff(v.z), f2tff(v.w));
    }
    for (int t = tid; t < 1024; t += 256) {
        int row = t >> 4, c4 = (t & 15) << 2;   // row = d
        float4 v = *(const float4*)(W + row*64 + c4);
        *(float4*)&Ws[row*LA + c4] =
            make_float4(f2tff(v.x), f2tff(v.y), f2tff(v.z), f2tff(v.w));
    }
    __syncthreads();

    const int w = tid >> 5, lane = tid & 31;
    const int g = lane >> 2, t4 = lane & 3;
    float acc[8][4] = {};
    const float* X0 = Xs + (16*w + g)*LA;
    #pragma unroll
    for (int ks = 0; ks < 8; ks++) {
        const int k = ks*8 + t4;
        unsigned a[4] = { uf(X0[k]), uf(X0[8*LA + k]), uf(X0[k+4]), uf(X0[8*LA + k+4]) };
        #pragma unroll
        for (int nt = 0; nt < 8; nt++) {
            const float* Wr = Ws + (nt*8 + g)*LA + k;
            unsigned bb[2] = { uf(Wr[0]), uf(Wr[4]) };
            mma8(acc[nt], a, bb);
        }
    }

    if (blockIdx.z == 0) {      // V: transposed store to g_vt[bh][d][s]
        const int s = s0 + 16*w + g;
        float* vt = g_vt + (size_t)bh*HEAD*Sx;
        #pragma unroll
        for (int nt = 0; nt < 8; nt++) {
            const int d = nt*8 + 2*t4;
            vt[(size_t)d*Sx + s]         = f2tff(acc[nt][0]);
            vt[(size_t)(d+1)*Sx + s]     = f2tff(acc[nt][1]);
            vt[(size_t)d*Sx + s + 8]     = f2tff(acc[nt][2]);
            vt[(size_t)(d+1)*Sx + s + 8] = f2tff(acc[nt][3]);
        }
    } else if (blockIdx.z == 1) {  // K: pair-packed d columns
        float* o0 = g_k + (size_t)bh*Sx*HEAD + (size_t)(s0 + 16*w + g)*HEAD;
        float* o1 = o0 + 8*HEAD;
        const int pp0 = (t4 < 2) ? 4*t4 : 4*t4 - 7;
        #pragma unroll
        for (int nt = 0; nt < 8; nt++) {
            o0[nt*8 + pp0]     = f2tff(acc[nt][0]);
            o0[nt*8 + pp0 + 2] = f2tff(acc[nt][1]);
            o1[nt*8 + pp0]     = f2tff(acc[nt][2]);
            o1[nt*8 + pp0 + 2] = f2tff(acc[nt][3]);
        }
    } else {                     // Q: natural
        float* o0 = g_q + (size_t)bh*Sx*HEAD + (size_t)(s0 + 16*w + g)*HEAD;
        float* o1 = o0 + 8*HEAD;
        #pragma unroll
        for (int nt = 0; nt < 8; nt++) {
            *(float2*)&o0[nt*8 + 2*t4] =
                make_float2(f2tff(acc[nt][0]), f2tff(acc[nt][1]));
            *(float2*)&o1[nt*8 + 2*t4] =
                make_float2(f2tff(acc[nt][2]), f2tff(acc[nt][3]));
        }
    }
}

// ============================================================
// Flash attention, tf32 mma, causal. grid (B*H, S/256), 256 thr,
// 1 CTA/SM. q-tile 256 (warp=32 rows), k-tile 64.
// Q packed a-frag-major; K pair-packed (LDS.64 b-frags);
// V TRANSPOSED in smem -> P c-frag reused directly as a-frag via
// the k-slot permutation (t4->2t4, t4+4->2t4+1): NO exchange at all.
// ============================================================
__global__ __launch_bounds__(256, 1) void attn_kernel()
{
    extern __shared__ float sm[];
    float* Qp = sm;                       // 8w x 2mt x 8ks x 32 x float4 = 16384 f
    float* KV = sm + 16384;               // 2 stages x (64*LP K + 64*LP Vt)
    const int KVST = 2*64*LP;             // 9216 floats per stage

    const int bh = blockIdx.x;
    const int qb = gridDim.y - 1 - blockIdx.y;   // big jobs first
    const int q0 = qb * 256;
    const int tid = threadIdx.x;
    const int w = tid >> 5, lane = tid & 31;
    const int g = lane >> 2, t4 = lane & 3;

    const float* Qg  = g_q  + (size_t)bh*Sx*HEAD + (size_t)q0*HEAD;
    const float* Kg  = g_k  + (size_t)bh*Sx*HEAD;
    const float* Vtg = g_vt + (size_t)bh*HEAD*Sx;
    const int ktN = 4*qb + 4;

    // ---- stage natural Q into KV region, pack a-frag-major ----
    {
        float* Qst = KV;   // 256 x LA = 17408 <= 18432
        #pragma unroll 4
        for (int t = tid; t < 4096; t += 256) {
            int row = t >> 4, c4 = (t & 15) << 2;
            cp16(s2u(&Qst[row*LA + c4]), Qg + row*64 + c4);
        }
        asm volatile("cp.async.commit_group;" ::: "memory");
        asm volatile("cp.async.wait_group 0;" ::: "memory");
        __syncthreads();
        #pragma unroll
        for (int mt = 0; mt < 2; mt++)
            #pragma unroll
            for (int ks = 0; ks < 8; ks++) {
                int r = 32*w + 16*mt + g;
                int k = 8*ks + t4;
                float4 v = make_float4(Qst[r*LA + k],     Qst[(r+8)*LA + k],
                                       Qst[r*LA + k + 4], Qst[(r+8)*LA + k + 4]);
                ((float4*)Qp)[((w*2 + mt)*8 + ks)*32 + lane] = v;
            }
        __syncthreads();
    }

    // ---- prefetch K/Vt tile 0 ----
    {
        float* Ks = KV, * Vs = KV + 64*LP;
        #pragma unroll
        for (int t = tid; t < 1024; t += 256) {
            int row = t >> 4, c4 = (t & 15) << 2;
            cp16(s2u(&Ks[row*LP + c4]), Kg + row*64 + c4);
            cp16(s2u(&Vs[row*LP + c4]), Vtg + (size_t)row*Sx + c4);
        }
        asm volatile("cp.async.commit_group;" ::: "memory");
    }

    float o[2][8][4] = {};
    float m_[4] = {-1e30f, -1e30f, -1e30f, -1e30f};
    float l_[4] = {};
    const int rwarp = q0 + 32*w;
    const float SC2 = 0.18033688011112042f;   // 0.125 * log2(e)
    const float4* QP = (const float4*)Qp;
    const int qbase0 = (w*2 + 0)*8*32;
    const int qbase1 = (w*2 + 1)*8*32;

    for (int kt = 0; kt < ktN; kt++) {
        const int cur = kt & 1;
        float* Kc = KV + cur*KVST;
        float* Vc = Kc + 64*LP;
        __syncthreads();
        if (kt + 1 < ktN) {
            float* Kn = KV + (cur^1)*KVST;
            float* Vn = Kn + 64*LP;
            #pragma unroll
            for (int t = tid; t < 1024; t += 256) {
                int row = t >> 4, c4 = (t & 15) << 2;
                cp16(s2u(&Kn[row*LP + c4]), Kg + (size_t)((kt+1)*64 + row)*64 + c4);
                cp16(s2u(&Vn[row*LP + c4]), Vtg + (size_t)row*Sx + (kt+1)*64 + c4);
            }
            asm volatile("cp.async.commit_group;" ::: "memory");
            asm volatile("cp.async.wait_group 1;" ::: "memory");
        } else {
            asm volatile("cp.async.wait_group 0;" ::: "memory");
        }
        __syncthreads();

        if (rwarp + 31 >= kt*64) {
            // ---- phase 1: S = Q K^T (K pair-packed -> LDS.64) ----
            float sc[2][8][4] = {};
            #pragma unroll
            for (int ks = 0; ks < 8; ks++) {
                float4 q0v = QP[qbase0 + ks*32 + lane];
                float4 q1v = QP[qbase1 + ks*32 + lane];
                unsigned a0[4] = { uf(q0v.x), uf(q0v.y), uf(q0v.z), uf(q0v.w) };
                unsigned a1[4] = { uf(q1v.x), uf(q1v.y), uf(q1v.z), uf(q1v.w) };
                #pragma unroll
                for (int nt = 0; nt < 8; nt++) {
                    float2 kb = *(const float2*)&Kc[(nt*8 + g)*LP + ks*8 + 2*t4];
                    unsigned bb[2] = { uf(kb.x), uf(kb.y) };
                    mma8(sc[0][nt], a0, bb);
                    mma8(sc[1][nt], a1, bb);
                }
            }
            // ---- scale (base-2) + causal mask ----
            #pragma unroll
            for (int mt = 0; mt < 2; mt++)
                #pragma unroll
                for (int nt = 0; nt < 8; nt++)
                    #pragma unroll
                    for (int i = 0; i < 4; i++)
                        sc[mt][nt][i] *= SC2;
            if (kt*64 + 63 > rwarp) {
                #pragma unroll
                for (int mt = 0; mt < 2; mt++) {
                    const int rA = rwarp + 16*mt + g, rB = rA + 8;
                    #pragma unroll
                    for (int nt = 0; nt < 8; nt++) {
                        int c = kt*64 + nt*8 + 2*t4;
                        if (c     > rA) sc[mt][nt][0] = -1e30f;
                        if (c + 1 > rA) sc[mt][nt][1] = -1e30f;
                        if (c     > rB) sc[mt][nt][2] = -1e30f;
                        if (c + 1 > rB) sc[mt][nt][3] = -1e30f;
                    }
                }
            }
            // ---- online softmax in registers (base-2) ----
            #pragma unroll
            for (int j = 0; j < 4; j++) {
                const int mt = j >> 1, p = j & 1;
                float mt0 = -1e30f;
                #pragma unroll
                for (int nt = 0; nt < 8; nt++)
                    mt0 = fmaxf(mt0, fmaxf(sc[mt][nt][2*p], sc[mt][nt][2*p+1]));
                mt0 = fmaxf(mt0, __shfl_xor_sync(0xffffffffu, mt0, 1));
                mt0 = fmaxf(mt0, __shfl_xor_sync(0xffffffffu, mt0, 2));
                float mn = fmaxf(m_[j], mt0);
                float f = ex2(m_[j] - mn);
                m_[j] = mn;
                float s = 0.f;
                #pragma unroll
                for (int nt = 0; nt < 8; nt++) {
                    float p0 = ex2(sc[mt][nt][2*p]   - mn);
                    float p1 = ex2(sc[mt][nt][2*p+1] - mn);
                    s += p0 + p1;
                    sc[mt][nt][2*p] = f2tff(p0); sc[mt][nt][2*p+1] = f2tff(p1);
                }
                s += __shfl_xor_sync(0xffffffffu, s, 1);
                s += __shfl_xor_sync(0xffffffffu, s, 2);
                l_[j] = l_[j]*f + s;
                #pragma unroll
                for (int nt = 0; nt < 8; nt++) {
                    o[mt][nt][2*p] *= f; o[mt][nt][2*p+1] *= f;
                }
            }
            // ---- phase 3: O += P V. c-frag IS the a-frag under the
            // k-slot permutation; V^T supplies matching LDS.64 b-frags ----
            #pragma unroll
            for (int ks = 0; ks < 8; ks++) {
                unsigned a0[4] = { uf(sc[0][ks][0]), uf(sc[0][ks][2]),
                                   uf(sc[0][ks][1]), uf(sc[0][ks][3]) };
                unsigned a1[4] = { uf(sc[1][ks][0]), uf(sc[1][ks][2]),
                                   uf(sc[1][ks][1]), uf(sc[1][ks][3]) };
                #pragma unroll
                for (int nt = 0; nt < 8; nt++) {
                    float2 vb = *(const float2*)&Vc[(nt*8 + g)*LP + ks*8 + 2*t4];
                    unsigned bb[2] = { uf(vb.x), uf(vb.y) };
                    mma8(o[0][nt], a0, bb);
                    mma8(o[1][nt], a1, bb);
                }
            }
        }
    }

    // ---- epilogue: normalize, tf32-round, scatter PAIR-PACKED ----
    const int b = bh >> 4, h = bh & 15;
    const int pp0 = (t4 < 2) ? 4*t4 : 4*t4 - 7;
    #pragma unroll
    for (int mt = 0; mt < 2; mt++) {
        float i0v = 1.0f / l_[2*mt], i1v = 1.0f / l_[2*mt+1];
        float* d0 = g_attn + (size_t)(b*Sx + q0 + 32*w + 16*mt + g)*EMBED + h*HEAD;
        float* d1 = d0 + (size_t)8*EMBED;
        #pragma unroll
        for (int nt = 0; nt < 8; nt++) {
            d0[nt*8 + pp0]     = f2tff(o[mt][nt][0]*i0v);
            d0[nt*8 + pp0 + 2] = f2tff(o[mt][nt][1]*i0v);
            d1[nt*8 + pp0]     = f2tff(o[mt][nt][2]*i1v);
            d1[nt*8 + pp0 + 2] = f2tff(o[mt][nt][3]*i1v);
        }
    }
}

// ============================================================
// Output projection. grid (EMBED/128, B*S/128), 256 thr, 2 CTAs/SM.
// M=128, N=128, k-chunk 32, cp.async DOUBLE-BUFFERED (32 iters,
// wait_group 1). A and W pair-packed -> all frag loads LDS.64;
// stage stride LO=40 keeps them conflict-free per half-warp.
// ============================================================
__global__ __launch_bounds__(256, 2) void outproj_kernel(
    const float* __restrict__ bo, float* __restrict__ out)
{
    extern __shared__ float sm[];
    const int SS = 2*128*LO;      // 10240 floats per stage (A + W)
    const int j0 = blockIdx.x * 128;
    const int r0 = blockIdx.y * 128;
    const int tid = threadIdx.x;
    const int w = tid >> 5, lane = tid & 31;
    const int g = lane >> 2, t4 = lane & 3;

    auto issue = [&](int stage, int e0) {
        float* As = sm + stage*SS;
        float* Wf = As + 128*LO;
        #pragma unroll 4
        for (int t = tid; t < 1024; t += 256) {
            int row = t >> 3, c4 = (t & 7) << 2;
            cp16(s2u(&As[row*LO + c4]),
                 g_attn + (size_t)(r0 + row)*EMBED + e0 + c4);
        }
        #pragma unroll 4
        for (int t = tid; t < 1024; t += 256) {
            int row = t >> 3, c4 = (t & 7) << 2;
            cp16(s2u(&Wf[row*LO + c4]),
                 g_wo + (size_t)(j0 + row)*EMBED + e0 + c4);
        }
        asm volatile("cp.async.commit_group;" ::: "memory");
    };

    issue(0, 0);

    float acc[16][4] = {};
    for (int et = 0; et < 32; et++) {
        const int cur = et & 1;
        if (et + 1 < 32) {
            issue(cur ^ 1, (et + 1) * 32);
            asm volatile("cp.async.wait_group 1;" ::: "memory");
        } else {
            asm volatile("cp.async.wait_group 0;" ::: "memory");
        }
        __syncthreads();

        const float* As = sm + cur*SS;
        const float* Wf = As + 128*LO;
        const float* A0 = As + (16*w + g)*LO;
        #pragma unroll
        for (int ks = 0; ks < 4; ks++) {
            float2 xa = *(const float2*)&A0[ks*8 + 2*t4];
            float2 ya = *(const float2*)&A0[8*LO + ks*8 + 2*t4];
            unsigned a[4] = { uf(xa.x), uf(ya.x), uf(xa.y), uf(ya.y) };
            #pragma unroll
            for (int nt = 0; nt < 16; nt++) {
                float2 wb = *(const float2*)&Wf[(nt*8 + g)*LO + ks*8 + 2*t4];
                unsigned bb[2] = { uf(wb.x), uf(wb.y) };
                mma8(acc[nt], a, bb);
            }
        }
        __syncthreads();   // done reading cur before next issue overwrites it
    }

    const int row = r0 + 16*w + g;
    #pragma unroll
    for (int nt = 0; nt < 16; nt++) {
        int j = j0 + nt*8 + 2*t4;
        float b0 = bo[j], b1 = bo[j + 1];
        *(float2*)&out[(size_t)row*EMBED + j] =
            make_float2(acc[nt][0] + b0, acc[nt][1] + b1);
        *(float2*)&out[(size_t)(row + 8)*EMBED + j] =
            make_float2(acc[nt][2] + b0, acc[nt][3] + b1);
    }
}

// ============================================================
extern "C" void kernel_launch(void* const* d_in, const int* in_sizes, int n_in,
                              void* d_out, int out_size)
{
    const float* values  = (const float*)d_in[0];
    const float* keys    = (const float*)d_in[1];
    const float* queries = (const float*)d_in[2];
    // d_in[3] = mask: known causal tril, applied analytically — ignored.
    const float* Wv = (const float*)d_in[4];
    const float* Wk = (const float*)d_in[5];
    const float* Wq = (const float*)d_in[6];
    const float* Wo = (const float*)d_in[7];
    const float* bo = (const float*)d_in[8];
    float* out = (float*)d_out;

    const int proj_smem  = (128 + 64) * LA * 4;              //  52224
    const int attn_smem  = (16384 + 2*2*64*LP) * 4;          // 139264
    const int oproj_smem = 2 * 2 * 128 * LO * 4;             //  81920
    cudaFuncSetAttribute(proj_kernel,
        cudaFuncAttributeMaxDynamicSharedMemorySize, proj_smem);
    cudaFuncSetAttribute(attn_kernel,
        cudaFuncAttributeMaxDynamicSharedMemorySize, attn_smem);
    cudaFuncSetAttribute(outproj_kernel,
        cudaFuncAttributeMaxDynamicSharedMemorySize, oproj_smem);

    dim3 pg(Sx/128, Bx*HEADS, 4);   // z==3 runs Wo prep
    proj_kernel<<<pg, 256, proj_smem>>>(values, keys, queries, Wv, Wk, Wq, Wo);

    dim3 ag(Bx*HEADS, Sx/256);
    attn_kernel<<<ag, 256, attn_smem>>>();

    dim3 og(EMBED/128, (Bx*Sx)/128);
    outproj_kernel<<<og, 256, oproj_smem>>>(bo, out);
}